// round 4
// baseline (speedup 1.0000x reference)
#include <cuda_runtime.h>
#include <cstddef>

#define LSEQ 256
#define NB   8
#define NC   64
#define ATOT 32768   // padded chart floats per batch (diag w padded to even len)

// t = max_c scores, padded-diagonal layout: g_td[b*ATOT + A(w) + i]
__device__ float g_td[NB * ATOT];

// A(w) = sum_{v<w} even-rounded(256 - v) = off1(w) + floor(w/2); always even.
__host__ __device__ __forceinline__ int a_of(int w) {
    return (w - 1) * 256 - (((w - 1) * w) >> 1) + (w >> 1);
}

// ---------------------------------------------------------------------------
// Kernel 1: t[b,i,e] = max over C of scores[b,i,e,:], upper triangle only.
// ---------------------------------------------------------------------------
__global__ void max_kernel(const float* __restrict__ scores) {
    const int i    = blockIdx.x;
    const int b    = blockIdx.y;
    const int warp = threadIdx.x >> 5;
    const int lane = threadIdx.x & 31;

    for (int e = i + 1 + warp; e < LSEQ; e += 8) {
        const float* p = scores + (((size_t)b * LSEQ + i) * LSEQ + e) * NC;
        float v = fmaxf(p[lane], p[lane + 32]);
        #pragma unroll
        for (int o = 16; o > 0; o >>= 1)
            v = fmaxf(v, __shfl_xor_sync(0xffffffffu, v, o));
        if (lane == 0)
            g_td[b * ATOT + a_of(e - i) + i] = v;
    }
}

// ---------------------------------------------------------------------------
// Kernel 2: CKY inside (max semiring), one 1024-thread CTA per batch.
// Thread = (g = tid>>7 in [0,8), u = tid&127) owning cells (2u, 2u+1).
// Left operand: LDS.64 always (diagonals even-aligned). Right operand:
// LDS.64 for even j, 2x LDS.32 for odd j (unroll-by-2 + parity peel).
// 8-way j-split partials in P; 128 threads combine + add prefetched t.
// ---------------------------------------------------------------------------
__global__ __launch_bounds__(1024, 1)
void dp_kernel(const int* __restrict__ lens, float* __restrict__ out) {
    const int b = blockIdx.x;
    extern __shared__ float S[];
    float*  D    = S;                                   // ATOT chart
    float2* P    = (float2*)(S + ATOT);                 // 8*128 partials
    int*    Atab = (int*)(S + ATOT + 2 * 8 * 128);      // A(w), w in [1,255]
    const float* tb  = g_td + b * ATOT;
    const int    tid = threadIdx.x;
    const int    u   = tid & 127;
    const int    g   = tid >> 7;
    const int    c0  = u << 1;

    if (tid >= 1 && tid < 256) Atab[tid] = a_of(tid);
    if (tid < 256) D[tid] = tb[tid];        // width-1 diag (incl. padding slot)
    __syncthreads();

    // Prefetch t for width 2 (combine threads, clamped float2).
    float2 tc = make_float2(0.f, 0.f);
    if (tid < 128) {
        int idx = 256 + (c0 < 252 ? c0 : 252);
        tc = *(const float2*)(tb + idx);
    }

    for (int w = 2; w < 256; ++w) {
        const int n = 256 - w;
        if (c0 < n) {
            float2 acc = make_float2(-1e30f, -1e30f);
            const int m   = w - 1;
            int       j   = 1 + ((g * m) >> 3);
            const int jhi = 1 + (((g + 1) * m) >> 3);
            if (j < jhi) {
                int lidx = Atab[j] + c0;            // left:  D[A(j) + c]
                int rw   = Atab[w - j] + c0 + j;    // right: D[A(w-j) + c + j]
                const int ce = w - 256 - ((w + 1) & 1);  // rw step from even j
                const int co = w - 256 - (w & 1);        // rw step from odd  j
                if (j & 1) {                         // parity peel (odd j)
                    float2 L = *(const float2*)(D + lidx);
                    float r0 = D[rw], r1 = D[rw + 1];
                    acc.x = fmaxf(acc.x, L.x + r0);
                    acc.y = fmaxf(acc.y, L.y + r1);
                    lidx += 257 - j;
                    rw   += co - j;
                    ++j;
                }
                for (; j + 1 < jhi; j += 2) {        // even j, then odd j+1
                    float2 L0 = *(const float2*)(D + lidx);
                    float2 R0 = *(const float2*)(D + rw);
                    acc.x = fmaxf(acc.x, L0.x + R0.x);
                    acc.y = fmaxf(acc.y, L0.y + R0.y);
                    int lidx1 = lidx + 256 - j;
                    int rw1   = rw + ce - j;
                    float2 L1 = *(const float2*)(D + lidx1);
                    float r0 = D[rw1], r1 = D[rw1 + 1];
                    acc.x = fmaxf(acc.x, L1.x + r0);
                    acc.y = fmaxf(acc.y, L1.y + r1);
                    lidx = lidx1 + 256 - j;          // 257 - (j+1)
                    rw   = rw1 + co - j - 1;         // co - (j+1)
                }
                if (j < jhi) {                       // tail (even j)
                    float2 L0 = *(const float2*)(D + lidx);
                    float2 R0 = *(const float2*)(D + rw);
                    acc.x = fmaxf(acc.x, L0.x + R0.x);
                    acc.y = fmaxf(acc.y, L0.y + R0.y);
                }
            }
            P[(g << 7) + u] = acc;
        }
        __syncthreads();

        if (tid < 128) {
            if (c0 < n) {
                float2 v = P[u];
                #pragma unroll
                for (int gg = 1; gg < 8; ++gg) {
                    float2 p = P[(gg << 7) + u];
                    v.x = fmaxf(v.x, p.x);
                    v.y = fmaxf(v.y, p.y);
                }
                v.x += tc.x; v.y += tc.y;
                *(float2*)(D + Atab[w] + c0) = v;
            }
            // Prefetch t for width w+1 (clamped; overlaps next bulk phase).
            int wn      = (w + 1 < 255) ? w + 1 : 255;
            int padlen  = (257 - wn) & ~1;
            int cl      = (c0 < padlen - 2) ? c0 : padlen - 2;
            tc = *(const float2*)(tb + Atab[wn] + cl);
        }
        __syncthreads();
    }

    if (tid == 0) {
        int len = lens[b];
        len = len < 1 ? 1 : (len > 255 ? 255 : len);
        out[b] = D[a_of(len)];               // s[0, len]
    }
}

// ---------------------------------------------------------------------------
extern "C" void kernel_launch(void* const* d_in, const int* in_sizes, int n_in,
                              void* d_out, int out_size) {
    const float* scores = (const float*)d_in[0];
    const int*   lens   = (const int*)d_in[1];
    float*       out    = (float*)d_out;
    (void)in_sizes; (void)n_in; (void)out_size;

    const int smem = ATOT * 4 + 8 * 128 * 8 + 256 * 4 + 64;
    cudaFuncSetAttribute(dp_kernel,
                         cudaFuncAttributeMaxDynamicSharedMemorySize, smem);

    max_kernel<<<dim3(LSEQ - 1, NB), 256>>>(scores);
    dp_kernel<<<NB, 1024, smem>>>(lens, out);
}

// round 5
// speedup vs baseline: 1.7699x; 1.7699x over previous
#include <cuda_runtime.h>
#include <cstddef>

#define LSEQ 256
#define NB   8
#define NC   64
#define TRI  32640   // packed upper triangle (e > i)

// t = max_c scores, row-packed layout: g_td[b*TRI + rs(i) + (e-i-1)]
__device__ float g_td[NB * TRI];

// rs(i) = sum_{r<i} (255 - r) = 255*i - i*(i-1)/2
__host__ __device__ __forceinline__ int rs_of(int i) {
    return i * 255 - ((i * (i - 1)) >> 1);
}

// ---------------------------------------------------------------------------
// Kernel 1: t[b,i,e] = max over C of scores[b,i,e,:], upper triangle only.
// ---------------------------------------------------------------------------
__global__ void max_kernel(const float* __restrict__ scores) {
    const int i    = blockIdx.x;          // 0 .. 254
    const int b    = blockIdx.y;
    const int warp = threadIdx.x >> 5;
    const int lane = threadIdx.x & 31;
    const int base = b * TRI + rs_of(i) - i - 1;

    for (int e = i + 1 + warp; e < LSEQ; e += 8) {
        const float* p = scores + (((size_t)b * LSEQ + i) * LSEQ + e) * NC;
        float v = fmaxf(p[lane], p[lane + 32]);
        #pragma unroll
        for (int o = 16; o > 0; o >>= 1)
            v = fmaxf(v, __shfl_xor_sync(0xffffffffu, v, o));
        if (lane == 0)
            g_td[base + e] = v;
    }
}

// ---------------------------------------------------------------------------
// Kernel 2: CKY inside (max semiring), one 1024-thread CTA per batch.
// Row-packed chart in SMEM. Per pass, TWO widths (w, w+1) share the bulk:
//   thread (g = tid>>8, c = tid&255) accumulates over its quarter of
//   j in [2, w-1]:  L = D[rs(c)+j-1] (stride-1 in j),
//                   R0 = D[rs(c+j)+w-j-1], R1 = R0's neighbor (+1 word).
// Combine (tid<256): width w = partials + j=1 fixup + t; partial barrier;
// width w+1 = partials + j=1 & j=w fixups (use fresh diag w) + t.
// ---------------------------------------------------------------------------
__global__ __launch_bounds__(1024, 1)
void dp_kernel(const int* __restrict__ lens, float* __restrict__ out) {
    const int b = blockIdx.x;
    extern __shared__ float S[];
    float* D   = S;                        // TRI chart
    float* Pw  = S + TRI;                  // 4*256 partials, width w
    float* Pw1 = Pw + 1024;                // 4*256 partials, width w+1
    int*   rs  = (int*)(Pw1 + 1024);       // rs(i), i in [0,255]
    const float* tb  = g_td + b * TRI;
    const int    tid = threadIdx.x;
    const int    c   = tid & 255;
    const int    g   = tid >> 8;

    if (tid < 256) rs[tid] = rs_of(tid);
    __syncthreads();
    const int rsc = rs[c];
    if (g == 0 && c < 255) D[rsc] = tb[rsc];     // width-1 diagonal
    __syncthreads();

    // Prefetch t for widths 2 and 3 (combine threads only), clamped.
    float tw = 0.f, tw1 = 0.f;
    if (tid < 256) {
        int i0 = rsc + 1; if (i0 > TRI - 1) i0 = TRI - 1;
        int i1 = rsc + 2; if (i1 > TRI - 1) i1 = TRI - 1;
        tw = tb[i0]; tw1 = tb[i1];
    }

    for (int w = 2; w < LSEQ; w += 2) {
        const int n = LSEQ - w;                  // cells at width w
        if (c < n) {
            float accw = -1e30f, accw1 = -1e30f;
            const int m   = w - 2;
            const int jlo = 2 + ((g * m) >> 2);
            const int jhi = 2 + (((g + 1) * m) >> 2);
            if (jlo < jhi) {
                int la = rsc + jlo - 1;          // left:  stride-1 in j
                int ra = rs[c + jlo] + w - jlo - 1;
                int st = 254 - c - jlo;          // ra step (decrements)
                #pragma unroll 4
                for (int j = jlo; j < jhi; ++j) {
                    const float L  = D[la];
                    const float R0 = D[ra];
                    const float R1 = D[ra + 1];
                    accw  = fmaxf(accw,  L + R0);
                    accw1 = fmaxf(accw1, L + R1);
                    la += 1;
                    ra += st; --st;
                }
            }
            Pw [(g << 8) + c] = accw;
            Pw1[(g << 8) + c] = accw1;
        }
        __syncthreads();

        if (tid < 256) {
            // ---- width w
            if (c < n) {
                float v = fmaxf(fmaxf(Pw[c],       Pw[256 + c]),
                                fmaxf(Pw[512 + c], Pw[768 + c]));
                // j = 1 (old diagonals): s[c,c+1] + s[c+1,c+w]
                v = fmaxf(v, D[rsc] + D[rs[c + 1] + w - 2]);
                D[rsc + w - 1] = v + tw;
            }
            asm volatile("bar.sync 1, 256;" ::: "memory");
            // ---- width w+1 (uses freshly written diagonal w)
            if (c < n - 1) {
                float v = fmaxf(fmaxf(Pw1[c],       Pw1[256 + c]),
                                fmaxf(Pw1[512 + c], Pw1[768 + c]));
                v = fmaxf(v, D[rsc] + D[rs[c + 1] + w - 1]);   // j = 1
                v = fmaxf(v, D[rsc + w - 1] + D[rs[c + w]]);   // j = w
                D[rsc + w] = v + tw1;
            }
            // Prefetch t for next pass (widths w+2, w+3), clamped.
            int i0 = rsc + w + 1; if (i0 > TRI - 1) i0 = TRI - 1;
            int i1 = rsc + w + 2; if (i1 > TRI - 1) i1 = TRI - 1;
            tw = tb[i0]; tw1 = tb[i1];
        }
        __syncthreads();
    }

    if (tid == 0) {
        int len = lens[b];
        len = len < 1 ? 1 : (len > 255 ? 255 : len);
        out[b] = D[len - 1];                 // s[0, len] = D[rs(0)+len-1]
    }
}

// ---------------------------------------------------------------------------
extern "C" void kernel_launch(void* const* d_in, const int* in_sizes, int n_in,
                              void* d_out, int out_size) {
    const float* scores = (const float*)d_in[0];
    const int*   lens   = (const int*)d_in[1];
    float*       out    = (float*)d_out;
    (void)in_sizes; (void)n_in; (void)out_size;

    const int smem = (TRI + 2 * 1024 + 256) * (int)sizeof(float);
    cudaFuncSetAttribute(dp_kernel,
                         cudaFuncAttributeMaxDynamicSharedMemorySize, smem);

    max_kernel<<<dim3(LSEQ - 1, NB), 256>>>(scores);
    dp_kernel<<<NB, 1024, smem>>>(lens, out);
}